// round 1
// baseline (speedup 1.0000x reference)
#include <cuda_runtime.h>
#include <math.h>

// ============================================================================
// PlainFCOS post-process: top-1000 of sigmoid(cls_pred[80M]) + box gather.
//
// Strategy:
//  - sigmoid is monotonic -> select on raw logits, sigmoid only the winners.
//  - Pass 1 (one 320MB read): collect candidates with logit > 3.5 into a
//    static device buffer (expected ~18k for N(0,1) logits).
//  - Check: if fewer than 1000 candidates, set a flag and re-collect at
//    threshold 2.0 (~1.8M candidates, fits 4M cap). Fallback kernel
//    early-outs when flag is 0 (the common case).
//  - Select: single block. 4x8-bit MSD radix-select over monotonic float
//    keys finds the exact 1000th value; compact key>=K* into shared; bitonic
//    sort 2048 x (key<<32 | ~index) descending -> exact jax.lax.top_k order
//    incl. lowest-index tie break. Then gather boxes, normalize, clip, write.
//
// Output layout assumed: [bboxes 1000x4][scores 1000][labels 1000] as f32.
// ============================================================================

#define K_TOP      1000
#define CAND_CAP   (1u << 22)   // 4M entries (32 MB static buffer)
#define SORT_CAP   2048
#define PRIMARY_THR  3.5f
#define FALLBACK_THR 2.0f

__device__ unsigned int g_ncand;
__device__ unsigned int g_flag;
__device__ uint2 g_cand[CAND_CAP];   // {monotonic key, flat index}

// Monotonic mapping: float -> uint32 preserving total order.
__device__ __forceinline__ unsigned int mono_key(float v) {
    unsigned int b = __float_as_uint(v);
    return b ^ ((b & 0x80000000u) ? 0xFFFFFFFFu : 0x80000000u);
}

__global__ void k_init() { g_ncand = 0u; g_flag = 0u; }

__global__ void k_check() {
    if (g_ncand < (unsigned)K_TOP) { g_flag = 1u; g_ncand = 0u; }
}

// Streaming candidate collection. need_flag=1 -> fallback pass (early-out
// unless g_flag was set by k_check).
__global__ void k_collect(const float* __restrict__ x, int n, float thr,
                          int need_flag) {
    if (need_flag && g_flag == 0u) return;

    const int n4 = n >> 2;
    const int stride = gridDim.x * blockDim.x;
    const float4* __restrict__ x4 = reinterpret_cast<const float4*>(x);
    int tid = blockIdx.x * blockDim.x + threadIdx.x;

    for (int i = tid; i < n4; i += stride) {
        float4 v = x4[i];
        unsigned int base = 4u * (unsigned int)i;
        if (v.x > thr) { unsigned p = atomicAdd(&g_ncand, 1u); if (p < CAND_CAP) g_cand[p] = make_uint2(mono_key(v.x), base + 0u); }
        if (v.y > thr) { unsigned p = atomicAdd(&g_ncand, 1u); if (p < CAND_CAP) g_cand[p] = make_uint2(mono_key(v.y), base + 1u); }
        if (v.z > thr) { unsigned p = atomicAdd(&g_ncand, 1u); if (p < CAND_CAP) g_cand[p] = make_uint2(mono_key(v.z), base + 2u); }
        if (v.w > thr) { unsigned p = atomicAdd(&g_ncand, 1u); if (p < CAND_CAP) g_cand[p] = make_uint2(mono_key(v.w), base + 3u); }
    }
    // tail (n not multiple of 4)
    int tail = n & 3;
    if (tid < tail) {
        int idx = (n4 << 2) + tid;
        float v = x[idx];
        if (v > thr) { unsigned p = atomicAdd(&g_ncand, 1u); if (p < CAND_CAP) g_cand[p] = make_uint2(mono_key(v), (unsigned)idx); }
    }
}

// img_w / img_h may arrive as int32 or float32 scalars; disambiguate by range.
__device__ __forceinline__ float load_dim(const void* p) {
    int iv = *(const int*)p;
    if (iv > 0 && iv < (1 << 27)) return (float)iv;
    return *(const float*)p;
}

__global__ void __launch_bounds__(1024, 1)
k_select(const float* __restrict__ box,
         const void* __restrict__ pw, const void* __restrict__ ph,
         int nc, float* __restrict__ out) {
    __shared__ unsigned int hist[256];
    __shared__ unsigned long long srt[SORT_CAP];
    __shared__ unsigned int s_cnt, s_prefix, s_remaining;

    const int tid = threadIdx.x;
    const unsigned int n = min(g_ncand, CAND_CAP);
    const unsigned int k = min((unsigned)K_TOP, n);

    if (tid == 0) { s_prefix = 0u; s_remaining = k; s_cnt = 0u; }
    __syncthreads();

    // ---- MSD radix select: find exact key of the k-th largest element ----
    if (k > 0) {
        for (int shift = 24; shift >= 0; shift -= 8) {
            for (int d = tid; d < 256; d += blockDim.x) hist[d] = 0u;
            __syncthreads();
            const unsigned int prefix = s_prefix;
            const unsigned int mask_hi =
                (shift == 24) ? 0u : (0xFFFFFFFFu << (shift + 8));
            for (unsigned i = tid; i < n; i += blockDim.x) {
                unsigned key = g_cand[i].x;
                if ((key & mask_hi) == prefix)
                    atomicAdd(&hist[(key >> shift) & 255u], 1u);
            }
            __syncthreads();
            if (tid == 0) {
                unsigned rem = s_remaining, cum = 0u;
                int d = 0;
                for (d = 255; d >= 0; d--) {
                    unsigned c = hist[d];
                    if (cum + c >= rem) break;
                    cum += c;
                }
                if (d < 0) d = 0;  // safety; cannot happen when counts consistent
                s_remaining = rem - cum;
                s_prefix = prefix | ((unsigned)d << shift);
            }
            __syncthreads();
        }
    }
    const unsigned int Kstar = s_prefix;

    // ---- compact all key >= K* into shared (at most ~k + few ties) ----
    if (k > 0) {
        for (unsigned i = tid; i < n; i += blockDim.x) {
            uint2 c = g_cand[i];
            if (c.x >= Kstar) {
                unsigned p = atomicAdd(&s_cnt, 1u);
                if (p < SORT_CAP)
                    srt[p] = ((unsigned long long)c.x << 32) |
                             (unsigned long long)(0xFFFFFFFFu - c.y);
            }
        }
    }
    __syncthreads();
    const unsigned int m = min(s_cnt, (unsigned)SORT_CAP);
    for (unsigned i = tid; i < SORT_CAP; i += blockDim.x)
        if (i >= m) srt[i] = 0ull;
    __syncthreads();

    // ---- bitonic sort SORT_CAP entries, descending ----
    for (unsigned sz = 2; sz <= SORT_CAP; sz <<= 1) {
        for (unsigned j = sz >> 1; j > 0; j >>= 1) {
            for (unsigned i = tid; i < SORT_CAP; i += blockDim.x) {
                unsigned ixj = i ^ j;
                if (ixj > i) {
                    unsigned long long a = srt[i], b = srt[ixj];
                    bool desc = ((i & sz) == 0u);
                    if (desc ? (a < b) : (a > b)) { srt[i] = b; srt[ixj] = a; }
                }
            }
            __syncthreads();
        }
    }

    // ---- decode winners, gather + normalize boxes, write outputs ----
    const float fw = load_dim(pw);
    const float fh = load_dim(ph);
    const unsigned int valid = min(k, m);
    const float4* __restrict__ box4 = reinterpret_cast<const float4*>(box);

    for (unsigned i = tid; i < (unsigned)K_TOP; i += blockDim.x) {
        float b0 = 0.f, b1 = 0.f, b2 = 0.f, b3 = 0.f, sc = 0.f, lab = 0.f;
        if (i < valid) {
            unsigned long long e = srt[i];
            unsigned key = (unsigned)(e >> 32);
            unsigned idx = 0xFFFFFFFFu - (unsigned)(e & 0xFFFFFFFFull);
            unsigned bits = (key & 0x80000000u) ? (key ^ 0x80000000u) : ~key;
            float v = __uint_as_float(bits);
            sc = 1.0f / (1.0f + expf(-v));
            unsigned bi = idx / (unsigned)nc;
            lab = (float)(idx - bi * (unsigned)nc);
            float4 bb = box4[bi];
            b0 = fminf(fmaxf(bb.x / fw, 0.f), 1.f);
            b1 = fminf(fmaxf(bb.y / fh, 0.f), 1.f);
            b2 = fminf(fmaxf(bb.z / fw, 0.f), 1.f);
            b3 = fminf(fmaxf(bb.w / fh, 0.f), 1.f);
        }
        out[i * 4 + 0] = b0;
        out[i * 4 + 1] = b1;
        out[i * 4 + 2] = b2;
        out[i * 4 + 3] = b3;
        out[4 * K_TOP + i] = sc;
        out[5 * K_TOP + i] = lab;
    }
}

extern "C" void kernel_launch(void* const* d_in, const int* in_sizes, int n_in,
                              void* d_out, int out_size) {
    const float* cls = (const float*)d_in[0];
    const float* box = (const float*)d_in[1];
    const void* pw = (n_in > 3) ? d_in[3] : nullptr;
    const void* ph = (n_in > 4) ? d_in[4] : nullptr;

    int n = in_sizes[0];                       // Nq * Nc
    int nbox = (n_in > 1) ? in_sizes[1] : 4;   // Nq * 4
    int nq = nbox / 4;
    int nc = (nq > 0) ? (n / nq) : 80;

    const int threads = 256;
    const int blocks = 1184;  // 148 SMs * 8

    k_init<<<1, 1>>>();
    k_collect<<<blocks, threads>>>(cls, n, PRIMARY_THR, 0);
    k_check<<<1, 1>>>();
    k_collect<<<blocks, threads>>>(cls, n, FALLBACK_THR, 1);
    k_select<<<1, 1024>>>(box, pw, ph, nc, (float*)d_out);
}

// round 4
// speedup vs baseline: 1.1694x; 1.1694x over previous
#include <cuda_runtime.h>
#include <math.h>

// ============================================================================
// PlainFCOS post-process: top-1000 of sigmoid(cls_pred[80M]) + box gather.
//
// R2 changes vs R1 (113us):
//  - collect unrolled x4 with front-batched independent float4 loads (MLP=4)
//    and a 16-wide fmax screen (common path: 16 elems -> 15 FMNMX + 1 branch,
//    all warp-wide, negligible vs memory).
//  - fallback pass collects the BAND (2.0, 3.5] and appends -> no duplicate
//    indices, no separate check kernel. Early-outs on g_ncand >= 1000.
//  - g_ncand zero-initialized at load, reset by k_select each call ->
//    k_init and k_check launches removed (3 launches total).
//  - radix-select digit scan parallelized (suffix Hillis-Steele, 8 steps)
//    instead of thread-0 serial 256-bin loop x4 passes.
// ============================================================================

#define K_TOP      1000
#define CAND_CAP   (1u << 22)   // 4M entries (32 MB static buffer)
#define SORT_CAP   2048
#define PRIMARY_THR  3.5f
#define BAND_LO      2.0f

__device__ unsigned int g_ncand;            // zero at module load; k_select resets
__device__ uint2 g_cand[CAND_CAP];          // {monotonic key, flat index}

// Monotonic mapping: float -> uint32 preserving total order.
__device__ __forceinline__ unsigned int mono_key(float v) {
    unsigned int b = __float_as_uint(v);
    return b ^ ((b & 0x80000000u) ? 0xFFFFFFFFu : 0x80000000u);
}

__device__ __forceinline__ void emit(float v, unsigned idx, float lo, float hi) {
    if (v > lo && v <= hi) {
        unsigned p = atomicAdd(&g_ncand, 1u);
        if (p < CAND_CAP) g_cand[p] = make_uint2(mono_key(v), idx);
    }
}

__device__ __forceinline__ float max4(float4 a) {
    return fmaxf(fmaxf(a.x, a.y), fmaxf(a.z, a.w));
}

__device__ __forceinline__ void scan4(float4 a, unsigned base, float lo, float hi) {
    if (max4(a) > lo) {
        emit(a.x, base + 0u, lo, hi);
        emit(a.y, base + 1u, lo, hi);
        emit(a.z, base + 2u, lo, hi);
        emit(a.w, base + 3u, lo, hi);
    }
}

// pass 0: collect v > 3.5.  pass 1: early-out if enough candidates, else
// append the band (2.0, 3.5]  (union = all v > 2.0, no duplicates).
__global__ void k_collect(const float* __restrict__ x, int n, int pass) {
    if (pass && g_ncand >= (unsigned)K_TOP) return;
    const float lo = pass ? BAND_LO : PRIMARY_THR;
    const float hi = pass ? PRIMARY_THR : __int_as_float(0x7f800000);  // +inf

    const int n4 = n >> 2;
    const float4* __restrict__ x4 = reinterpret_cast<const float4*>(x);
    const int stride = gridDim.x * blockDim.x;
    int i = blockIdx.x * blockDim.x + threadIdx.x;

    // main unrolled loop: 4 independent float4 loads in flight per warp
    for (; i + 3 * stride < n4; i += 4 * stride) {
        float4 a = x4[i];
        float4 b = x4[i + stride];
        float4 c = x4[i + 2 * stride];
        float4 d = x4[i + 3 * stride];
        float m = fmaxf(fmaxf(max4(a), max4(b)), fmaxf(max4(c), max4(d)));
        if (m > lo) {
            scan4(a, 4u * (unsigned)i, lo, hi);
            scan4(b, 4u * (unsigned)(i + stride), lo, hi);
            scan4(c, 4u * (unsigned)(i + 2 * stride), lo, hi);
            scan4(d, 4u * (unsigned)(i + 3 * stride), lo, hi);
        }
    }
    // remainder float4s
    for (; i < n4; i += stride)
        scan4(x4[i], 4u * (unsigned)i, lo, hi);
    // scalar tail (n not multiple of 4)
    {
        int tail = n & 3;
        int t = blockIdx.x * blockDim.x + threadIdx.x;
        if (t < tail) emit(x[(n4 << 2) + t], (unsigned)((n4 << 2) + t), lo, hi);
    }
}

// img_w / img_h may arrive as int32 or float32 scalars; disambiguate by range.
__device__ __forceinline__ float load_dim(const void* p) {
    int iv = *(const int*)p;
    if (iv > 0 && iv < (1 << 27)) return (float)iv;
    return *(const float*)p;
}

__global__ void __launch_bounds__(1024, 1)
k_select(const float* __restrict__ box,
         const void* __restrict__ pw, const void* __restrict__ ph,
         int nc, float* __restrict__ out) {
    __shared__ unsigned int hist[256];
    __shared__ unsigned int sc[257];
    __shared__ unsigned long long srt[SORT_CAP];
    __shared__ unsigned int s_cnt, s_prefix, s_remaining;

    const int tid = threadIdx.x;
    const unsigned int n = min(g_ncand, CAND_CAP);
    const unsigned int k = min((unsigned)K_TOP, n);

    if (tid == 0) { s_prefix = 0u; s_remaining = k; s_cnt = 0u; }
    __syncthreads();

    // ---- MSD radix select: exact key of the k-th largest element ----
    if (k > 0) {
        for (int shift = 24; shift >= 0; shift -= 8) {
            for (int d = tid; d < 256; d += blockDim.x) hist[d] = 0u;
            __syncthreads();
            const unsigned int prefix = s_prefix;
            const unsigned int mask_hi =
                (shift == 24) ? 0u : (0xFFFFFFFFu << (shift + 8));
            for (unsigned i = tid; i < n; i += blockDim.x) {
                unsigned key = g_cand[i].x;
                if ((key & mask_hi) == prefix)
                    atomicAdd(&hist[(key >> shift) & 255u], 1u);
            }
            __syncthreads();
            // suffix (from-top) inclusive scan: sc[d] = sum_{e>=d} hist[e]
            if (tid < 256) sc[tid] = hist[tid];
            __syncthreads();
            for (int off = 1; off < 256; off <<= 1) {
                unsigned add = 0u;
                if (tid < 256 && tid + off < 256) add = sc[tid + off];
                __syncthreads();
                if (tid < 256) sc[tid] += add;
                __syncthreads();
            }
            // find d: sc[d] >= rem && sc[d+1] < rem   (sc[256] = 0)
            if (tid < 256) {
                unsigned rem = s_remaining;
                unsigned here = sc[tid];
                unsigned above = (tid == 255) ? 0u : sc[tid + 1];
                if (here >= rem && above < rem) {
                    s_remaining = rem - above;
                    s_prefix = prefix | ((unsigned)tid << shift);
                }
            }
            __syncthreads();
        }
    }
    const unsigned int Kstar = s_prefix;

    // ---- compact all key >= K* into shared ----
    if (k > 0) {
        for (unsigned i = tid; i < n; i += blockDim.x) {
            uint2 c = g_cand[i];
            if (c.x >= Kstar) {
                unsigned p = atomicAdd(&s_cnt, 1u);
                if (p < SORT_CAP)
                    srt[p] = ((unsigned long long)c.x << 32) |
                             (unsigned long long)(0xFFFFFFFFu - c.y);
            }
        }
    }
    __syncthreads();
    const unsigned int m = min(s_cnt, (unsigned)SORT_CAP);
    for (unsigned i = tid; i < SORT_CAP; i += blockDim.x)
        if (i >= m) srt[i] = 0ull;
    __syncthreads();

    // ---- bitonic sort SORT_CAP entries, descending ----
    for (unsigned sz = 2; sz <= SORT_CAP; sz <<= 1) {
        for (unsigned j = sz >> 1; j > 0; j >>= 1) {
            for (unsigned i = tid; i < SORT_CAP; i += blockDim.x) {
                unsigned ixj = i ^ j;
                if (ixj > i) {
                    unsigned long long a = srt[i], b = srt[ixj];
                    bool desc = ((i & sz) == 0u);
                    if (desc ? (a < b) : (a > b)) { srt[i] = b; srt[ixj] = a; }
                }
            }
            __syncthreads();
        }
    }

    // ---- decode winners, gather + normalize boxes, write outputs ----
    const float fw = load_dim(pw);
    const float fh = load_dim(ph);
    const unsigned int valid = min(k, m);
    const float4* __restrict__ box4 = reinterpret_cast<const float4*>(box);

    for (unsigned i = tid; i < (unsigned)K_TOP; i += blockDim.x) {
        float b0 = 0.f, b1 = 0.f, b2 = 0.f, b3 = 0.f, scv = 0.f, lab = 0.f;
        if (i < valid) {
            unsigned long long e = srt[i];
            unsigned key = (unsigned)(e >> 32);
            unsigned idx = 0xFFFFFFFFu - (unsigned)(e & 0xFFFFFFFFull);
            unsigned bits = (key & 0x80000000u) ? (key ^ 0x80000000u) : ~key;
            float v = __uint_as_float(bits);
            scv = 1.0f / (1.0f + expf(-v));
            unsigned bi = idx / (unsigned)nc;
            lab = (float)(idx - bi * (unsigned)nc);
            float4 bb = box4[bi];
            b0 = fminf(fmaxf(bb.x / fw, 0.f), 1.f);
            b1 = fminf(fmaxf(bb.y / fh, 0.f), 1.f);
            b2 = fminf(fmaxf(bb.z / fw, 0.f), 1.f);
            b3 = fminf(fmaxf(bb.w / fh, 0.f), 1.f);
        }
        out[i * 4 + 0] = b0;
        out[i * 4 + 1] = b1;
        out[i * 4 + 2] = b2;
        out[i * 4 + 3] = b3;
        out[4 * K_TOP + i] = scv;
        out[5 * K_TOP + i] = lab;
    }

    // reset global state for the next graph replay (deterministic per call)
    __syncthreads();
    if (tid == 0) g_ncand = 0u;
}

extern "C" void kernel_launch(void* const* d_in, const int* in_sizes, int n_in,
                              void* d_out, int out_size) {
    const float* cls = (const float*)d_in[0];
    const float* box = (const float*)d_in[1];
    const void* pw = (n_in > 3) ? d_in[3] : nullptr;
    const void* ph = (n_in > 4) ? d_in[4] : nullptr;

    int n = in_sizes[0];                       // Nq * Nc
    int nbox = (n_in > 1) ? in_sizes[1] : 4;   // Nq * 4
    int nq = nbox / 4;
    int nc = (nq > 0) ? (n / nq) : 80;

    const int threads = 256;
    const int blocks = 1184;  // 148 SMs * 8

    k_collect<<<blocks, threads>>>(cls, n, 0);
    k_collect<<<blocks, threads>>>(cls, n, 1);
    k_select<<<1, 1024>>>(box, pw, ph, nc, (float*)d_out);
}

// round 6
// speedup vs baseline: 1.3994x; 1.1968x over previous
#include <cuda_runtime.h>
#include <math.h>

// ============================================================================
// PlainFCOS post-process: top-1000 of sigmoid(cls_pred[80M]) + box gather.
//
// R5 changes vs 96.7us version:
//  - k_select was barrier-bound (~145 block syncs x 32 warps ~= 30us).
//    * digit scan: warp-shuffle suffix scan (4 syncs/pass instead of 18)
//    * bitonic: j<32 steps are provably warp-local (thread t's pair lives in
//      [64w,64w+64)) -> __syncwarp; block syncs only for j>=32 (21 vs 66)
//    * radix pass loads unrolled x4 for MLP
//    * s_remaining/s_prefix double-buffered by pass parity (fixes race)
//  - k_collect unrolled x8 front-batched float4 loads.
// ============================================================================

#define K_TOP      1000
#define CAND_CAP   (1u << 22)   // 4M entries (32 MB static buffer)
#define SORT_CAP   2048
#define PRIMARY_THR  3.5f
#define BAND_LO      2.0f

__device__ unsigned int g_ncand;            // zero at module load; k_select resets
__device__ uint2 g_cand[CAND_CAP];          // {monotonic key, flat index}

__device__ __forceinline__ unsigned int mono_key(float v) {
    unsigned int b = __float_as_uint(v);
    return b ^ ((b & 0x80000000u) ? 0xFFFFFFFFu : 0x80000000u);
}

__device__ __forceinline__ void emit(float v, unsigned idx, float lo, float hi) {
    if (v > lo && v <= hi) {
        unsigned p = atomicAdd(&g_ncand, 1u);
        if (p < CAND_CAP) g_cand[p] = make_uint2(mono_key(v), idx);
    }
}

__device__ __forceinline__ float max4(float4 a) {
    return fmaxf(fmaxf(a.x, a.y), fmaxf(a.z, a.w));
}

__device__ __forceinline__ void scan4(float4 a, unsigned base, float lo, float hi) {
    if (max4(a) > lo) {
        emit(a.x, base + 0u, lo, hi);
        emit(a.y, base + 1u, lo, hi);
        emit(a.z, base + 2u, lo, hi);
        emit(a.w, base + 3u, lo, hi);
    }
}

// pass 0: collect v > 3.5.  pass 1: early-out if enough candidates, else
// append the band (2.0, 3.5]  (union = all v > 2.0, no duplicates).
__global__ void __launch_bounds__(256)
k_collect(const float* __restrict__ x, int n, int pass) {
    if (pass && g_ncand >= (unsigned)K_TOP) return;
    const float lo = pass ? BAND_LO : PRIMARY_THR;
    const float hi = pass ? PRIMARY_THR : __int_as_float(0x7f800000);  // +inf

    const int n4 = n >> 2;
    const float4* __restrict__ x4 = reinterpret_cast<const float4*>(x);
    const int stride = gridDim.x * blockDim.x;
    int i = blockIdx.x * blockDim.x + threadIdx.x;

    // main loop: 8 independent float4 loads in flight per thread
    for (; i + 7 * stride < n4; i += 8 * stride) {
        float4 v[8];
#pragma unroll
        for (int u = 0; u < 8; u++) v[u] = x4[i + u * stride];
        float m = max4(v[0]);
#pragma unroll
        for (int u = 1; u < 8; u++) m = fmaxf(m, max4(v[u]));
        if (m > lo) {
#pragma unroll
            for (int u = 0; u < 8; u++)
                scan4(v[u], 4u * (unsigned)(i + u * stride), lo, hi);
        }
    }
    for (; i < n4; i += stride)
        scan4(x4[i], 4u * (unsigned)i, lo, hi);
    {
        int tail = n & 3;
        int t = blockIdx.x * blockDim.x + threadIdx.x;
        if (t < tail) emit(x[(n4 << 2) + t], (unsigned)((n4 << 2) + t), lo, hi);
    }
}

// img_w / img_h may arrive as int32 or float32 scalars; disambiguate by range.
__device__ __forceinline__ float load_dim(const void* p) {
    int iv = *(const int*)p;
    if (iv > 0 && iv < (1 << 27)) return (float)iv;
    return *(const float*)p;
}

__global__ void __launch_bounds__(1024, 1)
k_select(const float* __restrict__ box,
         const void* __restrict__ pw, const void* __restrict__ ph,
         int nc, float* __restrict__ out) {
    __shared__ unsigned int hist[256];
    __shared__ unsigned int sc[256];
    __shared__ unsigned long long srt[SORT_CAP];
    __shared__ unsigned int s_cnt;
    __shared__ unsigned int s_pref[2], s_rem[2];   // double-buffered by pass parity

    const int tid = threadIdx.x;
    const unsigned int n = min(g_ncand, CAND_CAP);
    const unsigned int k = min((unsigned)K_TOP, n);

    if (tid == 0) { s_pref[0] = 0u; s_rem[0] = k; s_cnt = 0u; }
    __syncthreads();

    // ---- MSD radix select: exact key of the k-th largest element ----
    if (k > 0) {
        int par = 0;
        for (int shift = 24; shift >= 0; shift -= 8, par ^= 1) {
            if (tid < 256) hist[tid] = 0u;
            __syncthreads();
            const unsigned int prefix = s_pref[par];
            const unsigned int mask_hi =
                (shift == 24) ? 0u : (0xFFFFFFFFu << (shift + 8));
            // unrolled x4: 4 independent key loads in flight
            unsigned i = (unsigned)tid;
            const unsigned bs = 1024u;
            for (; i + 3u * bs < n; i += 4u * bs) {
                unsigned k0 = g_cand[i          ].x;
                unsigned k1 = g_cand[i +      bs].x;
                unsigned k2 = g_cand[i + 2u * bs].x;
                unsigned k3 = g_cand[i + 3u * bs].x;
                if ((k0 & mask_hi) == prefix) atomicAdd(&hist[(k0 >> shift) & 255u], 1u);
                if ((k1 & mask_hi) == prefix) atomicAdd(&hist[(k1 >> shift) & 255u], 1u);
                if ((k2 & mask_hi) == prefix) atomicAdd(&hist[(k2 >> shift) & 255u], 1u);
                if ((k3 & mask_hi) == prefix) atomicAdd(&hist[(k3 >> shift) & 255u], 1u);
            }
            for (; i < n; i += bs) {
                unsigned key = g_cand[i].x;
                if ((key & mask_hi) == prefix) atomicAdd(&hist[(key >> shift) & 255u], 1u);
            }
            __syncthreads();
            // warp 0: suffix scan of 256 bins (8 bins/lane, shuffle across lanes)
            if (tid < 32) {
                unsigned b[8], s[8];
#pragma unroll
                for (int j = 0; j < 8; j++) b[j] = hist[tid * 8 + j];
                s[7] = b[7];
#pragma unroll
                for (int j = 6; j >= 0; j--) s[j] = s[j + 1] + b[j];
                unsigned total = s[0];
                unsigned incl = total;
#pragma unroll
                for (int off = 1; off < 32; off <<= 1) {
                    unsigned v = __shfl_down_sync(0xFFFFFFFFu, incl, off);
                    if (tid + off < 32) incl += v;
                }
                unsigned above_lane = incl - total;  // sum over lanes > tid
#pragma unroll
                for (int j = 0; j < 8; j++) sc[tid * 8 + j] = s[j] + above_lane;
            }
            __syncthreads();
            // exactly one d satisfies sc[d] >= rem && sc[d+1] < rem  (sc[256]=0)
            if (tid < 256) {
                unsigned rem = s_rem[par];
                unsigned here = sc[tid];
                unsigned above = (tid == 255) ? 0u : sc[tid + 1];
                if (here >= rem && above < rem) {
                    s_rem[par ^ 1]  = rem - above;
                    s_pref[par ^ 1] = prefix | ((unsigned)tid << shift);
                }
            }
            __syncthreads();
        }
    }
    const unsigned int Kstar = s_pref[0];   // 4 passes -> parity back to 0

    // ---- compact all key >= K* into shared ----
    if (k > 0) {
        for (unsigned i = tid; i < n; i += 1024u) {
            uint2 c = g_cand[i];
            if (c.x >= Kstar) {
                unsigned p = atomicAdd(&s_cnt, 1u);
                if (p < SORT_CAP)
                    srt[p] = ((unsigned long long)c.x << 32) |
                             (unsigned long long)(0xFFFFFFFFu - c.y);
            }
        }
    }
    __syncthreads();
    const unsigned int m = min(s_cnt, (unsigned)SORT_CAP);
    for (unsigned i = tid; i < SORT_CAP; i += 1024u)
        if (i >= m) srt[i] = 0ull;
    __syncthreads();

    // ---- bitonic sort SORT_CAP=2048 entries, descending ----
    // 1024 threads, thread t owns pair (i, i|j) with i = ((t & ~(j-1)) << 1) | (t & (j-1)).
    // For j < 32 the 64-element region [64w, 64w+64) is touched only by warp w
    // across all consecutive small-j steps -> __syncwarp suffices there.
    for (unsigned sz = 2; sz <= SORT_CAP; sz <<= 1) {
        for (unsigned j = sz >> 1; j > 0; j >>= 1) {
            if (j >= 32) __syncthreads(); else __syncwarp();
            unsigned t = (unsigned)tid;
            unsigned i = ((t & ~(j - 1u)) << 1) | (t & (j - 1u));
            unsigned ixj = i | j;
            unsigned long long a = srt[i], b = srt[ixj];
            bool desc = ((i & sz) == 0u);
            if (desc ? (a < b) : (a > b)) { srt[i] = b; srt[ixj] = a; }
        }
    }
    __syncthreads();

    // ---- decode winners, gather + normalize boxes, write outputs ----
    const float fw = load_dim(pw);
    const float fh = load_dim(ph);
    const unsigned int valid = min(k, m);
    const float4* __restrict__ box4 = reinterpret_cast<const float4*>(box);

    for (unsigned i = tid; i < (unsigned)K_TOP; i += 1024u) {
        float b0 = 0.f, b1 = 0.f, b2 = 0.f, b3 = 0.f, scv = 0.f, lab = 0.f;
        if (i < valid) {
            unsigned long long e = srt[i];
            unsigned key = (unsigned)(e >> 32);
            unsigned idx = 0xFFFFFFFFu - (unsigned)(e & 0xFFFFFFFFull);
            unsigned bits = (key & 0x80000000u) ? (key ^ 0x80000000u) : ~key;
            float v = __uint_as_float(bits);
            scv = 1.0f / (1.0f + expf(-v));
            unsigned bi = idx / (unsigned)nc;
            lab = (float)(idx - bi * (unsigned)nc);
            float4 bb = box4[bi];
            b0 = fminf(fmaxf(bb.x / fw, 0.f), 1.f);
            b1 = fminf(fmaxf(bb.y / fh, 0.f), 1.f);
            b2 = fminf(fmaxf(bb.z / fw, 0.f), 1.f);
            b3 = fminf(fmaxf(bb.w / fh, 0.f), 1.f);
        }
        out[i * 4 + 0] = b0;
        out[i * 4 + 1] = b1;
        out[i * 4 + 2] = b2;
        out[i * 4 + 3] = b3;
        out[4 * K_TOP + i] = scv;
        out[5 * K_TOP + i] = lab;
    }

    // reset global state for the next graph replay (deterministic per call)
    __syncthreads();
    if (tid == 0) g_ncand = 0u;
}

extern "C" void kernel_launch(void* const* d_in, const int* in_sizes, int n_in,
                              void* d_out, int out_size) {
    const float* cls = (const float*)d_in[0];
    const float* box = (const float*)d_in[1];
    const void* pw = (n_in > 3) ? d_in[3] : nullptr;
    const void* ph = (n_in > 4) ? d_in[4] : nullptr;

    int n = in_sizes[0];                       // Nq * Nc
    int nbox = (n_in > 1) ? in_sizes[1] : 4;   // Nq * 4
    int nq = nbox / 4;
    int nc = (nq > 0) ? (n / nq) : 80;

    const int threads = 256;
    const int blocks = 1184;  // 148 SMs * 8

    k_collect<<<blocks, threads>>>(cls, n, 0);
    k_collect<<<blocks, threads>>>(cls, n, 1);
    k_select<<<1, 1024>>>(box, pw, ph, nc, (float*)d_out);
}

// round 7
// speedup vs baseline: 1.4277x; 1.0202x over previous
#include <cuda_runtime.h>
#include <math.h>

// ============================================================================
// PlainFCOS post-process: top-1000 of sigmoid(cls_pred[80M]) + box gather.
//
// R7: single persistent fused kernel (was 3 launches).
//  - 152 blocks x 1024 threads; grid-stride collect of logits > 3.5 into SoA
//    candidate buffers (expected ~18.6k of 80M for N(0,1)).
//  - ticket barrier (__threadfence + atomicAdd); LAST block runs selection:
//      * rare-path band re-scans (2.0,3.5], (-inf,2.0] if n < 1000 (never
//        taken on bench input; costs nothing when skipped)
//      * 4x8-bit MSD radix-select on monotonic keys (SoA, unroll x8)
//      * compact key >= K*; adaptive bitonic (1024 if m<=1024 else 2048)
//      * exact jax.lax.top_k order incl. lowest-index tie-break via
//        (key<<32 | ~idx) descending sort
//  - __ldcs streaming loads for the 320MB sweep (no reuse).
// Output layout: [bboxes 1000x4][scores 1000][labels 1000] as f32.
// ============================================================================

#define K_TOP      1000
#define CAND_CAP   (1u << 22)   // 4M entries
#define SORT_CAP   2048
#define PRIMARY_THR  3.5f
#define BAND_LO      2.0f
#define NBLOCKS    152
#define NTHREADS   1024

__device__ unsigned int g_ncand;   // zero at load; reset by last block each call
__device__ unsigned int g_done;    // ticket counter; reset by last block
__device__ unsigned int g_key[CAND_CAP];
__device__ unsigned int g_idx[CAND_CAP];

__device__ __forceinline__ unsigned int mono_key(float v) {
    unsigned int b = __float_as_uint(v);
    return b ^ ((b & 0x80000000u) ? 0xFFFFFFFFu : 0x80000000u);
}

__device__ __forceinline__ void emit(float v, unsigned idx, float lo, float hi) {
    if (v > lo && v <= hi) {
        unsigned p = atomicAdd(&g_ncand, 1u);
        if (p < CAND_CAP) { g_key[p] = mono_key(v); g_idx[p] = idx; }
    }
}

__device__ __forceinline__ float max4(float4 a) {
    return fmaxf(fmaxf(a.x, a.y), fmaxf(a.z, a.w));
}

__device__ __forceinline__ void scan4(float4 a, unsigned base, float lo, float hi) {
    if (max4(a) > lo) {
        emit(a.x, base + 0u, lo, hi);
        emit(a.y, base + 1u, lo, hi);
        emit(a.z, base + 2u, lo, hi);
        emit(a.w, base + 3u, lo, hi);
    }
}

__device__ __forceinline__ float load_dim(const void* p) {
    int iv = *(const int*)p;
    if (iv > 0 && iv < (1 << 27)) return (float)iv;
    return *(const float*)p;
}

__global__ void __launch_bounds__(NTHREADS, 1)
k_fused(const float* __restrict__ x, int n,
        const float* __restrict__ box,
        const void* __restrict__ pw, const void* __restrict__ ph,
        int nc, float* __restrict__ out) {
    __shared__ unsigned int hist[256];
    __shared__ unsigned int sc[256];
    __shared__ unsigned long long srt[SORT_CAP];
    __shared__ unsigned int s_cnt, s_ticket, s_n;
    __shared__ unsigned int s_pref[2], s_rem[2];

    const int tid = threadIdx.x;
    const int n4 = n >> 2;
    const float4* __restrict__ x4 = reinterpret_cast<const float4*>(x);
    const unsigned stride = gridDim.x * blockDim.x;

    // ================= phase 1: streaming collect (all blocks) =============
    {
        const float lo = PRIMARY_THR;
        const float hi = __int_as_float(0x7f800000);  // +inf
        unsigned i = blockIdx.x * blockDim.x + tid;
        for (; i + 7u * stride < (unsigned)n4; i += 8u * stride) {
            float4 v[8];
#pragma unroll
            for (int u = 0; u < 8; u++) v[u] = __ldcs(&x4[i + u * stride]);
            float m = max4(v[0]);
#pragma unroll
            for (int u = 1; u < 8; u++) m = fmaxf(m, max4(v[u]));
            if (m > lo) {
#pragma unroll
                for (int u = 0; u < 8; u++)
                    scan4(v[u], 4u * (i + u * stride), lo, hi);
            }
        }
        for (; i < (unsigned)n4; i += stride)
            scan4(__ldcs(&x4[i]), 4u * i, lo, hi);
        int tail = n & 3;
        unsigned t = blockIdx.x * blockDim.x + tid;
        if ((int)t < tail) emit(x[(n4 << 2) + t], (unsigned)((n4 << 2) + t), lo, hi);
    }

    // ================= ticket: last block proceeds to select ===============
    __syncthreads();
    if (tid == 0) {
        __threadfence();
        s_ticket = atomicAdd(&g_done, 1u);
    }
    __syncthreads();
    if (s_ticket != gridDim.x - 1u) return;
    __threadfence();   // acquire: make all blocks' candidate writes visible

    // ================= rare fallback bands (never taken on bench) ==========
    {
        const float blo[2] = { BAND_LO, -__int_as_float(0x7f800000) };
        const float bhi[2] = { PRIMARY_THR, BAND_LO };
        for (int b = 0; b < 2; b++) {
            if (tid == 0) s_n = g_ncand;
            __syncthreads();
            if (s_n >= (unsigned)K_TOP) break;
            for (unsigned i = tid; i < (unsigned)n4; i += NTHREADS)
                scan4(x4[i], 4u * i, blo[b], bhi[b]);
            int tail = n & 3;
            if (tid < tail) emit(x[(n4 << 2) + tid], (unsigned)((n4 << 2) + tid),
                                 blo[b], bhi[b]);
            __syncthreads();
        }
    }
    __syncthreads();

    const unsigned int nn = min(*(volatile unsigned int*)&g_ncand, CAND_CAP);
    const unsigned int k = min((unsigned)K_TOP, nn);
    if (tid == 0) { s_pref[0] = 0u; s_rem[0] = k; s_cnt = 0u; }
    __syncthreads();

    // ============== MSD radix select: key of the k-th largest ==============
    if (k > 0) {
        int par = 0;
        for (int shift = 24; shift >= 0; shift -= 8, par ^= 1) {
            if (tid < 256) hist[tid] = 0u;
            __syncthreads();
            const unsigned prefix = s_pref[par];
            const unsigned mask_hi =
                (shift == 24) ? 0u : (0xFFFFFFFFu << (shift + 8));
            unsigned i = (unsigned)tid;
            for (; i + 7u * NTHREADS < nn; i += 8u * NTHREADS) {
                unsigned kk[8];
#pragma unroll
                for (int u = 0; u < 8; u++) kk[u] = g_key[i + u * NTHREADS];
#pragma unroll
                for (int u = 0; u < 8; u++)
                    if ((kk[u] & mask_hi) == prefix)
                        atomicAdd(&hist[(kk[u] >> shift) & 255u], 1u);
            }
            for (; i < nn; i += NTHREADS) {
                unsigned key = g_key[i];
                if ((key & mask_hi) == prefix)
                    atomicAdd(&hist[(key >> shift) & 255u], 1u);
            }
            __syncthreads();
            // warp 0: suffix scan of 256 bins (8 bins/lane + lane shuffle)
            if (tid < 32) {
                unsigned b[8], s[8];
#pragma unroll
                for (int j = 0; j < 8; j++) b[j] = hist[tid * 8 + j];
                s[7] = b[7];
#pragma unroll
                for (int j = 6; j >= 0; j--) s[j] = s[j + 1] + b[j];
                unsigned total = s[0];
                unsigned incl = total;
#pragma unroll
                for (int off = 1; off < 32; off <<= 1) {
                    unsigned v = __shfl_down_sync(0xFFFFFFFFu, incl, off);
                    if (tid + off < 32) incl += v;
                }
                unsigned above_lane = incl - total;
#pragma unroll
                for (int j = 0; j < 8; j++) sc[tid * 8 + j] = s[j] + above_lane;
            }
            __syncthreads();
            if (tid < 256) {
                unsigned rem = s_rem[par];
                unsigned here = sc[tid];
                unsigned above = (tid == 255) ? 0u : sc[tid + 1];
                if (here >= rem && above < rem) {
                    s_rem[par ^ 1]  = rem - above;
                    s_pref[par ^ 1] = prefix | ((unsigned)tid << shift);
                }
            }
            __syncthreads();
        }
    }
    const unsigned int Kstar = s_pref[0];

    // ================= compact key >= K* into shared =======================
    if (k > 0) {
        for (unsigned i = tid; i < nn; i += NTHREADS) {
            unsigned key = g_key[i];
            if (key >= Kstar) {
                unsigned p = atomicAdd(&s_cnt, 1u);
                if (p < SORT_CAP)
                    srt[p] = ((unsigned long long)key << 32) |
                             (unsigned long long)(0xFFFFFFFFu - g_idx[i]);
            }
        }
    }
    __syncthreads();
    const unsigned int m = min(s_cnt, (unsigned)SORT_CAP);
    const unsigned int sort_n = (m <= 1024u) ? 1024u : (unsigned)SORT_CAP;
    for (unsigned i = tid; i < sort_n; i += NTHREADS)
        if (i >= m) srt[i] = 0ull;
    __syncthreads();

    // ============ bitonic sort sort_n entries, descending ==================
    // thread t owns pair (i, i|j), i = ((t & ~(j-1)) << 1) | (t & (j-1)).
    // j < 32 => pairs warp-local within [64w, 64w+64) -> __syncwarp only.
    {
        const unsigned pairs = sort_n >> 1;
        for (unsigned sz = 2; sz <= sort_n; sz <<= 1) {
            for (unsigned j = sz >> 1; j > 0; j >>= 1) {
                if (j >= 32) __syncthreads(); else __syncwarp();
                unsigned t = (unsigned)tid;
                if (t < pairs) {
                    unsigned i = ((t & ~(j - 1u)) << 1) | (t & (j - 1u));
                    unsigned ixj = i | j;
                    unsigned long long a = srt[i], b = srt[ixj];
                    bool desc = ((i & sz) == 0u);
                    if (desc ? (a < b) : (a > b)) { srt[i] = b; srt[ixj] = a; }
                }
            }
        }
    }
    __syncthreads();

    // ======= decode winners, gather + normalize boxes, write outputs =======
    const float fw = load_dim(pw);
    const float fh = load_dim(ph);
    const unsigned int valid = min(k, m);
    const float4* __restrict__ box4 = reinterpret_cast<const float4*>(box);

    for (unsigned i = tid; i < (unsigned)K_TOP; i += NTHREADS) {
        float b0 = 0.f, b1 = 0.f, b2 = 0.f, b3 = 0.f, scv = 0.f, lab = 0.f;
        if (i < valid) {
            unsigned long long e = srt[i];
            unsigned key = (unsigned)(e >> 32);
            unsigned idx = 0xFFFFFFFFu - (unsigned)(e & 0xFFFFFFFFull);
            unsigned bits = (key & 0x80000000u) ? (key ^ 0x80000000u) : ~key;
            float v = __uint_as_float(bits);
            scv = 1.0f / (1.0f + expf(-v));
            unsigned bi = idx / (unsigned)nc;
            lab = (float)(idx - bi * (unsigned)nc);
            float4 bb = box4[bi];
            b0 = fminf(fmaxf(bb.x / fw, 0.f), 1.f);
            b1 = fminf(fmaxf(bb.y / fh, 0.f), 1.f);
            b2 = fminf(fmaxf(bb.z / fw, 0.f), 1.f);
            b3 = fminf(fmaxf(bb.w / fh, 0.f), 1.f);
        }
        out[i * 4 + 0] = b0;
        out[i * 4 + 1] = b1;
        out[i * 4 + 2] = b2;
        out[i * 4 + 3] = b3;
        out[4 * K_TOP + i] = scv;
        out[5 * K_TOP + i] = lab;
    }

    // reset globals for the next graph replay
    __syncthreads();
    if (tid == 0) { g_ncand = 0u; g_done = 0u; }
}

extern "C" void kernel_launch(void* const* d_in, const int* in_sizes, int n_in,
                              void* d_out, int out_size) {
    const float* cls = (const float*)d_in[0];
    const float* box = (const float*)d_in[1];
    const void* pw = (n_in > 3) ? d_in[3] : nullptr;
    const void* ph = (n_in > 4) ? d_in[4] : nullptr;

    int n = in_sizes[0];                       // Nq * Nc
    int nbox = (n_in > 1) ? in_sizes[1] : 4;   // Nq * 4
    int nq = nbox / 4;
    int nc = (nq > 0) ? (n / nq) : 80;

    k_fused<<<NBLOCKS, NTHREADS>>>(cls, n, box, pw, ph, nc, (float*)d_out);
}

// round 8
// speedup vs baseline: 1.6620x; 1.1641x over previous
#include <cuda_runtime.h>
#include <math.h>

// ============================================================================
// PlainFCOS post-process: top-1000 of sigmoid(cls_pred[80M]) + box gather.
//
// R8 changes vs R7 (79.2us; select tail ~25us was the bottleneck):
//  - gate tightened 3.5 -> 4.0: expected survivors 18.6k -> ~2.5k
//    (>=1000 at 30 sigma; exact fallback bands keep correctness universal).
//  - collect restored to the R6-proven 6.16TB/s shape (1184x256, plain LDG).
//  - fallback folded into k_select (band scans (2,4], (-inf,2] by the select
//    block, never taken on bench input) -> no 1184-block early-out launch.
//  - adaptive bitonic: m ~= 1000 + ties -> sort 1024 wide (15 block syncs).
// Output layout: [bboxes 1000x4][scores 1000][labels 1000] as f32.
// ============================================================================

#define K_TOP      1000
#define CAND_CAP   (1u << 22)   // 4M entries
#define SORT_CAP   2048
#define PRIMARY_THR  4.0f
#define BAND_LO      2.0f
#define SEL_THREADS  1024

__device__ unsigned int g_ncand;   // zero at load; k_select resets each call
__device__ unsigned int g_key[CAND_CAP];
__device__ unsigned int g_idx[CAND_CAP];

__device__ __forceinline__ unsigned int mono_key(float v) {
    unsigned int b = __float_as_uint(v);
    return b ^ ((b & 0x80000000u) ? 0xFFFFFFFFu : 0x80000000u);
}

__device__ __forceinline__ void emit(float v, unsigned idx, float lo, float hi) {
    if (v > lo && v <= hi) {
        unsigned p = atomicAdd(&g_ncand, 1u);
        if (p < CAND_CAP) { g_key[p] = mono_key(v); g_idx[p] = idx; }
    }
}

__device__ __forceinline__ float max4(float4 a) {
    return fmaxf(fmaxf(a.x, a.y), fmaxf(a.z, a.w));
}

__device__ __forceinline__ void scan4(float4 a, unsigned base, float lo, float hi) {
    if (max4(a) > lo) {
        emit(a.x, base + 0u, lo, hi);
        emit(a.y, base + 1u, lo, hi);
        emit(a.z, base + 2u, lo, hi);
        emit(a.w, base + 3u, lo, hi);
    }
}

// Streaming collect: v > 4.0.  (R6-proven shape: 1184 x 256, unroll x8.)
__global__ void __launch_bounds__(256)
k_collect(const float* __restrict__ x, int n) {
    const float lo = PRIMARY_THR;
    const float hi = __int_as_float(0x7f800000);  // +inf

    const int n4 = n >> 2;
    const float4* __restrict__ x4 = reinterpret_cast<const float4*>(x);
    const int stride = gridDim.x * blockDim.x;
    int i = blockIdx.x * blockDim.x + threadIdx.x;

    for (; i + 7 * stride < n4; i += 8 * stride) {
        float4 v[8];
#pragma unroll
        for (int u = 0; u < 8; u++) v[u] = x4[i + u * stride];
        float m = max4(v[0]);
#pragma unroll
        for (int u = 1; u < 8; u++) m = fmaxf(m, max4(v[u]));
        if (m > lo) {
#pragma unroll
            for (int u = 0; u < 8; u++)
                scan4(v[u], 4u * (unsigned)(i + u * stride), lo, hi);
        }
    }
    for (; i < n4; i += stride)
        scan4(x4[i], 4u * (unsigned)i, lo, hi);
    {
        int tail = n & 3;
        int t = blockIdx.x * blockDim.x + threadIdx.x;
        if (t < tail) emit(x[(n4 << 2) + t], (unsigned)((n4 << 2) + t), lo, hi);
    }
}

// img_w / img_h may arrive as int32 or float32 scalars; disambiguate by range.
__device__ __forceinline__ float load_dim(const void* p) {
    int iv = *(const int*)p;
    if (iv > 0 && iv < (1 << 27)) return (float)iv;
    return *(const float*)p;
}

__global__ void __launch_bounds__(SEL_THREADS, 1)
k_select(const float* __restrict__ x, int n,
         const float* __restrict__ box,
         const void* __restrict__ pw, const void* __restrict__ ph,
         int nc, float* __restrict__ out) {
    __shared__ unsigned int hist[256];
    __shared__ unsigned int sc[256];
    __shared__ unsigned long long srt[SORT_CAP];
    __shared__ unsigned int s_cnt, s_n;
    __shared__ unsigned int s_pref[2], s_rem[2];

    const int tid = threadIdx.x;
    const int n4 = n >> 2;
    const float4* __restrict__ x4 = reinterpret_cast<const float4*>(x);

    // ---- rare fallback bands (never taken on bench input) ----
    {
        if (tid == 0) s_n = g_ncand;
        __syncthreads();
        if (s_n < (unsigned)K_TOP) {
            const float blo[2] = { BAND_LO, -__int_as_float(0x7f800000) };
            const float bhi[2] = { PRIMARY_THR, BAND_LO };
            for (int b = 0; b < 2; b++) {
                if (s_n >= (unsigned)K_TOP) break;
                for (unsigned i = tid; i < (unsigned)n4; i += SEL_THREADS)
                    scan4(x4[i], 4u * i, blo[b], bhi[b]);
                int tail = n & 3;
                if (tid < tail)
                    emit(x[(n4 << 2) + tid], (unsigned)((n4 << 2) + tid),
                         blo[b], bhi[b]);
                __syncthreads();
                if (tid == 0) s_n = g_ncand;
                __syncthreads();
            }
        }
    }

    const unsigned int nn = min(*(volatile unsigned int*)&g_ncand, CAND_CAP);
    const unsigned int k = min((unsigned)K_TOP, nn);
    if (tid == 0) { s_pref[0] = 0u; s_rem[0] = k; s_cnt = 0u; }
    __syncthreads();

    // ---- MSD radix select: exact key of the k-th largest ----
    if (k > 0) {
        int par = 0;
        for (int shift = 24; shift >= 0; shift -= 8, par ^= 1) {
            if (tid < 256) hist[tid] = 0u;
            __syncthreads();
            const unsigned prefix = s_pref[par];
            const unsigned mask_hi =
                (shift == 24) ? 0u : (0xFFFFFFFFu << (shift + 8));
            unsigned i = (unsigned)tid;
            for (; i + 3u * SEL_THREADS < nn; i += 4u * SEL_THREADS) {
                unsigned kk[4];
#pragma unroll
                for (int u = 0; u < 4; u++) kk[u] = g_key[i + u * SEL_THREADS];
#pragma unroll
                for (int u = 0; u < 4; u++)
                    if ((kk[u] & mask_hi) == prefix)
                        atomicAdd(&hist[(kk[u] >> shift) & 255u], 1u);
            }
            for (; i < nn; i += SEL_THREADS) {
                unsigned key = g_key[i];
                if ((key & mask_hi) == prefix)
                    atomicAdd(&hist[(key >> shift) & 255u], 1u);
            }
            __syncthreads();
            // warp 0: suffix scan of 256 bins (8 bins/lane + lane shuffle)
            if (tid < 32) {
                unsigned b[8], s[8];
#pragma unroll
                for (int j = 0; j < 8; j++) b[j] = hist[tid * 8 + j];
                s[7] = b[7];
#pragma unroll
                for (int j = 6; j >= 0; j--) s[j] = s[j + 1] + b[j];
                unsigned total = s[0];
                unsigned incl = total;
#pragma unroll
                for (int off = 1; off < 32; off <<= 1) {
                    unsigned v = __shfl_down_sync(0xFFFFFFFFu, incl, off);
                    if (tid + off < 32) incl += v;
                }
                unsigned above_lane = incl - total;
#pragma unroll
                for (int j = 0; j < 8; j++) sc[tid * 8 + j] = s[j] + above_lane;
            }
            __syncthreads();
            if (tid < 256) {
                unsigned rem = s_rem[par];
                unsigned here = sc[tid];
                unsigned above = (tid == 255) ? 0u : sc[tid + 1];
                if (here >= rem && above < rem) {
                    s_rem[par ^ 1]  = rem - above;
                    s_pref[par ^ 1] = prefix | ((unsigned)tid << shift);
                }
            }
            __syncthreads();
        }
    }
    const unsigned int Kstar = s_pref[0];

    // ---- compact key >= K* into shared ----
    if (k > 0) {
        for (unsigned i = tid; i < nn; i += SEL_THREADS) {
            unsigned key = g_key[i];
            if (key >= Kstar) {
                unsigned p = atomicAdd(&s_cnt, 1u);
                if (p < SORT_CAP)
                    srt[p] = ((unsigned long long)key << 32) |
                             (unsigned long long)(0xFFFFFFFFu - g_idx[i]);
            }
        }
    }
    __syncthreads();
    const unsigned int m = min(s_cnt, (unsigned)SORT_CAP);
    const unsigned int sort_n = (m <= 1024u) ? 1024u : (unsigned)SORT_CAP;
    for (unsigned i = tid; i < sort_n; i += SEL_THREADS)
        if (i >= m) srt[i] = 0ull;
    __syncthreads();

    // ---- bitonic sort sort_n entries, descending ----
    // thread t owns pair (i, i|j), i = ((t & ~(j-1)) << 1) | (t & (j-1)).
    // j < 32 => pairs warp-local within [64w, 64w+64) -> __syncwarp only.
    {
        const unsigned pairs = sort_n >> 1;
        for (unsigned sz = 2; sz <= sort_n; sz <<= 1) {
            for (unsigned j = sz >> 1; j > 0; j >>= 1) {
                if (j >= 32) __syncthreads(); else __syncwarp();
                unsigned t = (unsigned)tid;
                if (t < pairs) {
                    unsigned i = ((t & ~(j - 1u)) << 1) | (t & (j - 1u));
                    unsigned ixj = i | j;
                    unsigned long long a = srt[i], b = srt[ixj];
                    bool desc = ((i & sz) == 0u);
                    if (desc ? (a < b) : (a > b)) { srt[i] = b; srt[ixj] = a; }
                }
            }
        }
    }
    __syncthreads();

    // ---- decode winners, gather + normalize boxes, write outputs ----
    const float fw = load_dim(pw);
    const float fh = load_dim(ph);
    const unsigned int valid = min(k, m);
    const float4* __restrict__ box4 = reinterpret_cast<const float4*>(box);

    for (unsigned i = tid; i < (unsigned)K_TOP; i += SEL_THREADS) {
        float b0 = 0.f, b1 = 0.f, b2 = 0.f, b3 = 0.f, scv = 0.f, lab = 0.f;
        if (i < valid) {
            unsigned long long e = srt[i];
            unsigned key = (unsigned)(e >> 32);
            unsigned idx = 0xFFFFFFFFu - (unsigned)(e & 0xFFFFFFFFull);
            unsigned bits = (key & 0x80000000u) ? (key ^ 0x80000000u) : ~key;
            float v = __uint_as_float(bits);
            scv = 1.0f / (1.0f + expf(-v));
            unsigned bi = idx / (unsigned)nc;
            lab = (float)(idx - bi * (unsigned)nc);
            float4 bb = box4[bi];
            b0 = fminf(fmaxf(bb.x / fw, 0.f), 1.f);
            b1 = fminf(fmaxf(bb.y / fh, 0.f), 1.f);
            b2 = fminf(fmaxf(bb.z / fw, 0.f), 1.f);
            b3 = fminf(fmaxf(bb.w / fh, 0.f), 1.f);
        }
        out[i * 4 + 0] = b0;
        out[i * 4 + 1] = b1;
        out[i * 4 + 2] = b2;
        out[i * 4 + 3] = b3;
        out[4 * K_TOP + i] = scv;
        out[5 * K_TOP + i] = lab;
    }

    // reset global state for the next graph replay
    __syncthreads();
    if (tid == 0) g_ncand = 0u;
}

extern "C" void kernel_launch(void* const* d_in, const int* in_sizes, int n_in,
                              void* d_out, int out_size) {
    const float* cls = (const float*)d_in[0];
    const float* box = (const float*)d_in[1];
    const void* pw = (n_in > 3) ? d_in[3] : nullptr;
    const void* ph = (n_in > 4) ? d_in[4] : nullptr;

    int n = in_sizes[0];                       // Nq * Nc
    int nbox = (n_in > 1) ? in_sizes[1] : 4;   // Nq * 4
    int nq = nbox / 4;
    int nc = (nq > 0) ? (n / nq) : 80;

    k_collect<<<1184, 256>>>(cls, n);
    k_select<<<1, SEL_THREADS>>>(cls, n, box, pw, ph, nc, (float*)d_out);
}